// round 3
// baseline (speedup 1.0000x reference)
#include <cuda_runtime.h>
#include <cstdint>
#include <math.h>

#define H_DIM 4096
#define E_DIM 64
#define BM 64
#define BK 32
#define PAD 65
#define GAP_THRESH 3e-4f

// flag list for near-tie tokens (no device allocation allowed -> globals)
__device__ int g_flag_count;
__device__ int g_flag_tokens[32768];

__global__ void reset_flags() { g_flag_count = 0; }

// ---------------------------------------------------------------------------
// GEMM: C[T, 64] = A[T, 4096] @ W[64, 4096]^T   (all fp32)
// ---------------------------------------------------------------------------
__global__ __launch_bounds__(256) void router_gemm(const float* __restrict__ A,
                                                   const float* __restrict__ W,
                                                   float* __restrict__ C) {
    __shared__ float As[BK * PAD];
    __shared__ float Ws[BK * PAD];

    const int tid = threadIdx.x;
    const int tx = tid & 15;
    const int ty = tid >> 4;

    const long tokenBase = (long)blockIdx.x * BM;
    const float* Ablk = A + tokenBase * H_DIM;

    float acc[4][4];
#pragma unroll
    for (int i = 0; i < 4; i++)
#pragma unroll
        for (int j = 0; j < 4; j++) acc[i][j] = 0.0f;

    const int id0 = tid,       row0 = id0 >> 3, c40 = id0 & 7;
    const int id1 = tid + 256, row1 = id1 >> 3, c41 = id1 & 7;

    float4 pa0, pa1, pw0, pw1;
    pa0 = *(const float4*)(Ablk + (long)row0 * H_DIM + c40 * 4);
    pa1 = *(const float4*)(Ablk + (long)row1 * H_DIM + c41 * 4);
    pw0 = *(const float4*)(W + (long)row0 * H_DIM + c40 * 4);
    pw1 = *(const float4*)(W + (long)row1 * H_DIM + c41 * 4);

    const int NT = H_DIM / BK;
    for (int t = 0; t < NT; t++) {
        As[(c40 * 4 + 0) * PAD + row0] = pa0.x;
        As[(c40 * 4 + 1) * PAD + row0] = pa0.y;
        As[(c40 * 4 + 2) * PAD + row0] = pa0.z;
        As[(c40 * 4 + 3) * PAD + row0] = pa0.w;
        As[(c41 * 4 + 0) * PAD + row1] = pa1.x;
        As[(c41 * 4 + 1) * PAD + row1] = pa1.y;
        As[(c41 * 4 + 2) * PAD + row1] = pa1.z;
        As[(c41 * 4 + 3) * PAD + row1] = pa1.w;
        Ws[(c40 * 4 + 0) * PAD + row0] = pw0.x;
        Ws[(c40 * 4 + 1) * PAD + row0] = pw0.y;
        Ws[(c40 * 4 + 2) * PAD + row0] = pw0.z;
        Ws[(c40 * 4 + 3) * PAD + row0] = pw0.w;
        Ws[(c41 * 4 + 0) * PAD + row1] = pw1.x;
        Ws[(c41 * 4 + 1) * PAD + row1] = pw1.y;
        Ws[(c41 * 4 + 2) * PAD + row1] = pw1.z;
        Ws[(c41 * 4 + 3) * PAD + row1] = pw1.w;
        __syncthreads();

        if (t + 1 < NT) {
            const int k0 = (t + 1) * BK;
            pa0 = *(const float4*)(Ablk + (long)row0 * H_DIM + k0 + c40 * 4);
            pa1 = *(const float4*)(Ablk + (long)row1 * H_DIM + k0 + c41 * 4);
            pw0 = *(const float4*)(W + (long)row0 * H_DIM + k0 + c40 * 4);
            pw1 = *(const float4*)(W + (long)row1 * H_DIM + k0 + c41 * 4);
        }

#pragma unroll
        for (int k = 0; k < BK; k++) {
            float a0 = As[k * PAD + ty * 4 + 0];
            float a1 = As[k * PAD + ty * 4 + 1];
            float a2 = As[k * PAD + ty * 4 + 2];
            float a3 = As[k * PAD + ty * 4 + 3];
            float w0 = Ws[k * PAD + tx * 4 + 0];
            float w1 = Ws[k * PAD + tx * 4 + 1];
            float w2 = Ws[k * PAD + tx * 4 + 2];
            float w3 = Ws[k * PAD + tx * 4 + 3];
            acc[0][0] += a0 * w0; acc[0][1] += a0 * w1; acc[0][2] += a0 * w2; acc[0][3] += a0 * w3;
            acc[1][0] += a1 * w0; acc[1][1] += a1 * w1; acc[1][2] += a1 * w2; acc[1][3] += a1 * w3;
            acc[2][0] += a2 * w0; acc[2][1] += a2 * w1; acc[2][2] += a2 * w2; acc[2][3] += a2 * w3;
            acc[3][0] += a3 * w0; acc[3][1] += a3 * w1; acc[3][2] += a3 * w2; acc[3][3] += a3 * w3;
        }
        __syncthreads();
    }

    float* Crow = C + tokenBase * E_DIM;
#pragma unroll
    for (int i = 0; i < 4; i++) {
        float4 v = make_float4(acc[i][0], acc[i][1], acc[i][2], acc[i][3]);
        *(float4*)(Crow + (long)(ty * 4 + i) * E_DIM + tx * 4) = v;
    }
}

// ---------------------------------------------------------------------------
// Softmax + provisional top-2; flags tokens whose top-3 logit gaps are too
// small to be decided reliably in fp32.
// ---------------------------------------------------------------------------
__global__ __launch_bounds__(256) void softmax_top2(const float* __restrict__ C,
                                                    float* __restrict__ P,
                                                    float* __restrict__ IDX, int T) {
    const int gwarp = (blockIdx.x * blockDim.x + threadIdx.x) >> 5;
    const int lane = threadIdx.x & 31;
    if (gwarp >= T) return;

    const float* row = C + (long)gwarp * E_DIM;
    float v0 = row[lane];
    float v1 = row[lane + 32];

    float m = fmaxf(v0, v1);
#pragma unroll
    for (int o = 16; o; o >>= 1) m = fmaxf(m, __shfl_xor_sync(0xffffffffu, m, o));

    float e0 = __expf(v0 - m);
    float e1 = __expf(v1 - m);
    float s = e0 + e1;
#pragma unroll
    for (int o = 16; o; o >>= 1) s += __shfl_xor_sync(0xffffffffu, s, o);
    float inv = 1.0f / s;

    float* prow = P + (long)gwarp * E_DIM;
    prow[lane] = e0 * inv;
    prow[lane + 32] = e1 * inv;

    // top-1
    float bv; int bi;
    if (v0 >= v1) { bv = v0; bi = lane; } else { bv = v1; bi = lane + 32; }
#pragma unroll
    for (int o = 16; o; o >>= 1) {
        float ov = __shfl_xor_sync(0xffffffffu, bv, o);
        int   oi = __shfl_xor_sync(0xffffffffu, bi, o);
        if (ov > bv || (ov == bv && oi < bi)) { bv = ov; bi = oi; }
    }
    // top-2
    float c0 = (lane == bi) ? -INFINITY : v0;
    float c1 = (lane + 32 == bi) ? -INFINITY : v1;
    float sv; int si;
    if (c0 >= c1) { sv = c0; si = lane; } else { sv = c1; si = lane + 32; }
#pragma unroll
    for (int o = 16; o; o >>= 1) {
        float ov = __shfl_xor_sync(0xffffffffu, sv, o);
        int   oi = __shfl_xor_sync(0xffffffffu, si, o);
        if (ov > sv || (ov == sv && oi < si)) { sv = ov; si = oi; }
    }
    // top-3 (value only, for the rank2/rank3 gap)
    float d0 = (lane == bi || lane == si) ? -INFINITY : v0;
    float d1 = (lane + 32 == bi || lane + 32 == si) ? -INFINITY : v1;
    float tv = fmaxf(d0, d1);
#pragma unroll
    for (int o = 16; o; o >>= 1) tv = fmaxf(tv, __shfl_xor_sync(0xffffffffu, tv, o));

    if (lane == 0) {
        IDX[(long)gwarp * 2 + 0] = (float)bi;
        IDX[(long)gwarp * 2 + 1] = (float)si;
        if ((bv - sv) < GAP_THRESH || (sv - tv) < GAP_THRESH) {
            int slot = atomicAdd(&g_flag_count, 1);
            if (slot < 32768) g_flag_tokens[slot] = gwarp;
        }
    }
}

// ---------------------------------------------------------------------------
// Exact (fp64) recomputation for flagged near-tie tokens. One CTA (64 thr)
// per token iteration; thread e owns expert e. Top-2 is re-decided on
// FLOAT-ROUNDED affinities with the jax tie rule (lower index wins).
// ---------------------------------------------------------------------------
__global__ __launch_bounds__(64) void refine_ties(const float* __restrict__ A,
                                                  const float* __restrict__ W,
                                                  float* __restrict__ IDX) {
    __shared__ float sA[H_DIM];
    __shared__ double sLog[E_DIM];

    const int n = g_flag_count;
    const int nclamp = n < 32768 ? n : 32768;

    for (int it = blockIdx.x; it < nclamp; it += gridDim.x) {
        const int tok = g_flag_tokens[it];
        const float* arow = A + (long)tok * H_DIM;
        for (int k = threadIdx.x * 4; k < H_DIM; k += 64 * 4)
            *(float4*)(sA + k) = *(const float4*)(arow + k);
        __syncthreads();

        const int e = threadIdx.x;
        const float* wrow = W + (long)e * H_DIM;
        double acc = 0.0;
#pragma unroll 4
        for (int k = 0; k < H_DIM; k += 4) {
            float4 w4 = *(const float4*)(wrow + k);
            acc = fma((double)sA[k + 0], (double)w4.x, acc);
            acc = fma((double)sA[k + 1], (double)w4.y, acc);
            acc = fma((double)sA[k + 2], (double)w4.z, acc);
            acc = fma((double)sA[k + 3], (double)w4.w, acc);
        }
        sLog[e] = acc;
        __syncthreads();

        if (threadIdx.x == 0) {
            double m = sLog[0];
            for (int i = 1; i < E_DIM; i++) m = sLog[i] > m ? sLog[i] : m;
            double s = 0.0;
            double ex[E_DIM];
            for (int i = 0; i < E_DIM; i++) { ex[i] = exp(sLog[i] - m); s += ex[i]; }
            // float-rounded affinities: emulate jax top_k over fp32 softmax
            float af[E_DIM];
            for (int i = 0; i < E_DIM; i++) af[i] = (float)(ex[i] / s);

            int bi = 0;
            for (int i = 1; i < E_DIM; i++)
                if (af[i] > af[bi]) bi = i;  // lower index kept on ties
            int si = (bi == 0) ? 1 : 0;
            for (int i = 0; i < E_DIM; i++) {
                if (i == bi || i == si) continue;
                if (af[i] > af[si]) si = i;
            }
            IDX[(long)tok * 2 + 0] = (float)bi;
            IDX[(long)tok * 2 + 1] = (float)si;
        }
        __syncthreads();
    }
}

// ---------------------------------------------------------------------------
// d_out: [logits T*64 | affinities T*64 | indices-as-float T*2], fp32.
// ---------------------------------------------------------------------------
extern "C" void kernel_launch(void* const* d_in, const int* in_sizes, int n_in,
                              void* d_out, int out_size) {
    const float* A = (const float*)d_in[0];
    const float* W = (const float*)d_in[1];
    const int T = in_sizes[0] / H_DIM;

    float* out = (float*)d_out;
    float* logits = out;
    float* affin  = out + (long)T * E_DIM;
    float* idx    = out + 2L * T * E_DIM;

    reset_flags<<<1, 1>>>();
    router_gemm<<<T / BM, 256>>>(A, W, logits);
    const int blocks = (T * 32 + 255) / 256;
    softmax_top2<<<blocks, 256>>>(logits, affin, idx, T);
    refine_ties<<<128, 64>>>(A, W, idx);
}

// round 4
// speedup vs baseline: 1.0381x; 1.0381x over previous
#include <cuda_runtime.h>
#include <cstdint>
#include <math.h>

#define H_DIM 4096
#define E_DIM 64
#define BM 64
#define BK 32
#define PAD 65       // smem K-tile stride (conflict-free transposed stores)
#define CPAD 68      // smem C-tile stride (16B-aligned rows, conflict-free reads)
#define GAP_THRESH 3e-4f

// flag list for near-tie tokens (no device allocation allowed -> globals)
__device__ int g_flag_count;
__device__ int g_flag_tokens[32768];

__global__ void reset_flags() { g_flag_count = 0; }

// ---------------------------------------------------------------------------
// Fused GEMM + softmax + top-2 + near-tie flagging.
// C[T,64] = A[T,4096] @ W[64,4096]^T (fp32). CTA: 64 tokens x 64 experts.
// Epilogue: stage logits in smem; each of 8 warps does softmax/top-2 for 8
// tokens; flags tokens whose top-3 logit gaps are < GAP_THRESH.
// ---------------------------------------------------------------------------
__global__ __launch_bounds__(256) void router_gemm_fused(const float* __restrict__ A,
                                                         const float* __restrict__ W,
                                                         float* __restrict__ C,
                                                         float* __restrict__ P,
                                                         float* __restrict__ IDX) {
    __shared__ float As[BK * PAD];
    __shared__ float Ws[BK * PAD];
    __shared__ float Cs[BM * CPAD];

    const int tid = threadIdx.x;
    const int tx = tid & 15;   // expert group
    const int ty = tid >> 4;   // token group

    const long tokenBase = (long)blockIdx.x * BM;
    const float* Ablk = A + tokenBase * H_DIM;

    float acc[4][4];
#pragma unroll
    for (int i = 0; i < 4; i++)
#pragma unroll
        for (int j = 0; j < 4; j++) acc[i][j] = 0.0f;

    const int id0 = tid,       row0 = id0 >> 3, c40 = id0 & 7;
    const int id1 = tid + 256, row1 = id1 >> 3, c41 = id1 & 7;

    float4 pa0, pa1, pw0, pw1;
    pa0 = *(const float4*)(Ablk + (long)row0 * H_DIM + c40 * 4);
    pa1 = *(const float4*)(Ablk + (long)row1 * H_DIM + c41 * 4);
    pw0 = *(const float4*)(W + (long)row0 * H_DIM + c40 * 4);
    pw1 = *(const float4*)(W + (long)row1 * H_DIM + c41 * 4);

    const int NT = H_DIM / BK;
    for (int t = 0; t < NT; t++) {
        As[(c40 * 4 + 0) * PAD + row0] = pa0.x;
        As[(c40 * 4 + 1) * PAD + row0] = pa0.y;
        As[(c40 * 4 + 2) * PAD + row0] = pa0.z;
        As[(c40 * 4 + 3) * PAD + row0] = pa0.w;
        As[(c41 * 4 + 0) * PAD + row1] = pa1.x;
        As[(c41 * 4 + 1) * PAD + row1] = pa1.y;
        As[(c41 * 4 + 2) * PAD + row1] = pa1.z;
        As[(c41 * 4 + 3) * PAD + row1] = pa1.w;
        Ws[(c40 * 4 + 0) * PAD + row0] = pw0.x;
        Ws[(c40 * 4 + 1) * PAD + row0] = pw0.y;
        Ws[(c40 * 4 + 2) * PAD + row0] = pw0.z;
        Ws[(c40 * 4 + 3) * PAD + row0] = pw0.w;
        Ws[(c41 * 4 + 0) * PAD + row1] = pw1.x;
        Ws[(c41 * 4 + 1) * PAD + row1] = pw1.y;
        Ws[(c41 * 4 + 2) * PAD + row1] = pw1.z;
        Ws[(c41 * 4 + 3) * PAD + row1] = pw1.w;
        __syncthreads();

        if (t + 1 < NT) {
            const int k0 = (t + 1) * BK;
            pa0 = *(const float4*)(Ablk + (long)row0 * H_DIM + k0 + c40 * 4);
            pa1 = *(const float4*)(Ablk + (long)row1 * H_DIM + k0 + c41 * 4);
            pw0 = *(const float4*)(W + (long)row0 * H_DIM + k0 + c40 * 4);
            pw1 = *(const float4*)(W + (long)row1 * H_DIM + k0 + c41 * 4);
        }

#pragma unroll
        for (int k = 0; k < BK; k++) {
            float a0 = As[k * PAD + ty * 4 + 0];
            float a1 = As[k * PAD + ty * 4 + 1];
            float a2 = As[k * PAD + ty * 4 + 2];
            float a3 = As[k * PAD + ty * 4 + 3];
            float w0 = Ws[k * PAD + tx * 4 + 0];
            float w1 = Ws[k * PAD + tx * 4 + 1];
            float w2 = Ws[k * PAD + tx * 4 + 2];
            float w3 = Ws[k * PAD + tx * 4 + 3];
            acc[0][0] += a0 * w0; acc[0][1] += a0 * w1; acc[0][2] += a0 * w2; acc[0][3] += a0 * w3;
            acc[1][0] += a1 * w0; acc[1][1] += a1 * w1; acc[1][2] += a1 * w2; acc[1][3] += a1 * w3;
            acc[2][0] += a2 * w0; acc[2][1] += a2 * w1; acc[2][2] += a2 * w2; acc[2][3] += a2 * w3;
            acc[3][0] += a3 * w0; acc[3][1] += a3 * w1; acc[3][2] += a3 * w2; acc[3][3] += a3 * w3;
        }
        __syncthreads();
    }

    // epilogue: logits to gmem + smem stage
    float* Crow = C + tokenBase * E_DIM;
#pragma unroll
    for (int i = 0; i < 4; i++) {
        float4 v = make_float4(acc[i][0], acc[i][1], acc[i][2], acc[i][3]);
        *(float4*)(Crow + (long)(ty * 4 + i) * E_DIM + tx * 4) = v;
        *(float4*)(Cs + (ty * 4 + i) * CPAD + tx * 4) = v;
    }
    __syncthreads();

    // softmax + top-2 + flagging: warp w handles tokens 8w..8w+7
    const int lane = tid & 31;
    const int wrp = tid >> 5;
#pragma unroll 1
    for (int t8 = 0; t8 < 8; t8++) {
        const int tok = wrp * 8 + t8;
        const float v0 = Cs[tok * CPAD + lane];
        const float v1 = Cs[tok * CPAD + lane + 32];

        float m = fmaxf(v0, v1);
#pragma unroll
        for (int o = 16; o; o >>= 1) m = fmaxf(m, __shfl_xor_sync(0xffffffffu, m, o));

        float e0 = __expf(v0 - m);
        float e1 = __expf(v1 - m);
        float s = e0 + e1;
#pragma unroll
        for (int o = 16; o; o >>= 1) s += __shfl_xor_sync(0xffffffffu, s, o);
        float inv = 1.0f / s;

        float* prow = P + (tokenBase + tok) * E_DIM;
        prow[lane] = e0 * inv;
        prow[lane + 32] = e1 * inv;

        // top-1 (ties -> lower index)
        float bv; int bi;
        if (v0 >= v1) { bv = v0; bi = lane; } else { bv = v1; bi = lane + 32; }
#pragma unroll
        for (int o = 16; o; o >>= 1) {
            float ov = __shfl_xor_sync(0xffffffffu, bv, o);
            int   oi = __shfl_xor_sync(0xffffffffu, bi, o);
            if (ov > bv || (ov == bv && oi < bi)) { bv = ov; bi = oi; }
        }
        // top-2
        float c0 = (lane == bi) ? -INFINITY : v0;
        float c1 = (lane + 32 == bi) ? -INFINITY : v1;
        float sv; int si;
        if (c0 >= c1) { sv = c0; si = lane; } else { sv = c1; si = lane + 32; }
#pragma unroll
        for (int o = 16; o; o >>= 1) {
            float ov = __shfl_xor_sync(0xffffffffu, sv, o);
            int   oi = __shfl_xor_sync(0xffffffffu, si, o);
            if (ov > sv || (ov == sv && oi < si)) { sv = ov; si = oi; }
        }
        // top-3 value (for rank2/rank3 gap)
        float d0 = (lane == bi || lane == si) ? -INFINITY : v0;
        float d1 = (lane + 32 == bi || lane + 32 == si) ? -INFINITY : v1;
        float tv = fmaxf(d0, d1);
#pragma unroll
        for (int o = 16; o; o >>= 1) tv = fmaxf(tv, __shfl_xor_sync(0xffffffffu, tv, o));

        if (lane == 0) {
            const long gtok = tokenBase + tok;
            IDX[gtok * 2 + 0] = (float)bi;
            IDX[gtok * 2 + 1] = (float)si;
            if ((bv - sv) < GAP_THRESH || (sv - tv) < GAP_THRESH) {
                int slot = atomicAdd(&g_flag_count, 1);
                if (slot < 32768) g_flag_tokens[slot] = (int)gtok;
            }
        }
    }
}

// ---------------------------------------------------------------------------
// Exact (fp64) recomputation for flagged near-tie tokens.
// 64 threads (= experts); 8 independent fp64 accumulators per thread to break
// the DFMA dependency chain; one parallel exp per thread; warp-shuffle
// max/sum; thread-0 top-2 on float-rounded affinities (jax tie rule).
// ---------------------------------------------------------------------------
__global__ __launch_bounds__(64) void refine_ties(const float* __restrict__ A,
                                                  const float* __restrict__ W,
                                                  float* __restrict__ IDX) {
    __shared__ float sA[H_DIM];
    __shared__ double dred[2];
    __shared__ double dred2[2];
    __shared__ float af_s[E_DIM];

    int n = g_flag_count;
    if (n > 32768) n = 32768;

    const int e = threadIdx.x;
    const int lane = e & 31;
    const int wrp = e >> 5;

    for (int it = blockIdx.x; it < n; it += gridDim.x) {
        const int tok = g_flag_tokens[it];
        const float* arow = A + (long)tok * H_DIM;
        for (int k = threadIdx.x * 4; k < H_DIM; k += 64 * 4)
            *(float4*)(sA + k) = *(const float4*)(arow + k);
        __syncthreads();

        const float* wrow = W + (long)e * H_DIM;
        double a0 = 0, a1 = 0, a2 = 0, a3 = 0, a4 = 0, a5 = 0, a6 = 0, a7 = 0;
#pragma unroll 4
        for (int k = 0; k < H_DIM; k += 8) {
            float4 w0 = *(const float4*)(wrow + k);
            float4 w1 = *(const float4*)(wrow + k + 4);
            a0 = fma((double)sA[k + 0], (double)w0.x, a0);
            a1 = fma((double)sA[k + 1], (double)w0.y, a1);
            a2 = fma((double)sA[k + 2], (double)w0.z, a2);
            a3 = fma((double)sA[k + 3], (double)w0.w, a3);
            a4 = fma((double)sA[k + 4], (double)w1.x, a4);
            a5 = fma((double)sA[k + 5], (double)w1.y, a5);
            a6 = fma((double)sA[k + 6], (double)w1.z, a6);
            a7 = fma((double)sA[k + 7], (double)w1.w, a7);
        }
        double l = ((a0 + a1) + (a2 + a3)) + ((a4 + a5) + (a6 + a7));

        // max over 64 logits: warp shuffle + cross-warp via smem
        double mv = l;
#pragma unroll
        for (int o = 16; o; o >>= 1) {
            double ov = __shfl_xor_sync(0xffffffffu, mv, o);
            mv = ov > mv ? ov : mv;
        }
        if (lane == 0) dred[wrp] = mv;
        __syncthreads();
        const double m = dred[0] > dred[1] ? dred[0] : dred[1];

        const double ex = exp(l - m);  // one exp per thread, in parallel
        double sm = ex;
#pragma unroll
        for (int o = 16; o; o >>= 1) sm += __shfl_xor_sync(0xffffffffu, sm, o);
        if (lane == 0) dred2[wrp] = sm;
        __syncthreads();
        const double s = dred2[0] + dred2[1];

        af_s[e] = (float)(ex / s);
        __syncthreads();

        if (e == 0) {
            int bi = 0;
#pragma unroll
            for (int i = 1; i < E_DIM; i++)
                if (af_s[i] > af_s[bi]) bi = i;  // ties keep lower index
            int si = (bi == 0) ? 1 : 0;
#pragma unroll
            for (int i = 0; i < E_DIM; i++) {
                if (i == bi || i == si) continue;
                if (af_s[i] > af_s[si]) si = i;
            }
            IDX[(long)tok * 2 + 0] = (float)bi;
            IDX[(long)tok * 2 + 1] = (float)si;
        }
        __syncthreads();
    }
}

// ---------------------------------------------------------------------------
// d_out: [logits T*64 | affinities T*64 | indices-as-float T*2], fp32.
// ---------------------------------------------------------------------------
extern "C" void kernel_launch(void* const* d_in, const int* in_sizes, int n_in,
                              void* d_out, int out_size) {
    const float* A = (const float*)d_in[0];
    const float* W = (const float*)d_in[1];
    const int T = in_sizes[0] / H_DIM;

    float* out = (float*)d_out;
    float* logits = out;
    float* affin  = out + (long)T * E_DIM;
    float* idx    = out + 2L * T * E_DIM;

    reset_flags<<<1, 1>>>();
    router_gemm_fused<<<T / BM, 256>>>(A, W, logits, affin, idx);
    refine_ties<<<128, 64>>>(A, W, idx);
}

// round 6
// speedup vs baseline: 1.5236x; 1.4677x over previous
#include <cuda_runtime.h>
#include <cuda_bf16.h>
#include <cstdint>
#include <math.h>

#define H_DIM 4096
#define E_DIM 64
#define TILE_M 128
#define KCHUNK 32
#define NCHUNKS (H_DIM / KCHUNK)   // 128
#define GAP_THRESH 5e-4f
#define CPAD 68

// smem stage (bytes): bf16 tiles, row stride 40 elems = 80 B (conflict-free:
// gcd(80,128)=16 -> 8 consecutive rows land on 8 distinct 16B bank groups)
#define RSTRIDE 80
#define OFF_AHI 0
#define OFF_ALO 10240
#define OFF_BHI 20480
#define OFF_BLO 25600
#define SMEM_BYTES 34816         // max(stage 30720, C-stage 128*68*4)

__device__ __forceinline__ uint32_t smem_to_u32(const void* p) {
    uint32_t a;
    asm("{ .reg .u64 t; cvta.to.shared.u64 t, %1; cvt.u32.u64 %0, t; }" : "=r"(a) : "l"(p));
    return a;
}

#define LDSM_X4(r0, r1, r2, r3, addr)                                          \
    asm volatile("ldmatrix.sync.aligned.m8n8.x4.shared.b16 {%0,%1,%2,%3}, [%4];" \
                 : "=r"(r0), "=r"(r1), "=r"(r2), "=r"(r3) : "r"(addr))

__device__ __forceinline__ void mma_bf16(float* c, const uint32_t* a,
                                         uint32_t b0, uint32_t b1) {
    asm volatile(
        "mma.sync.aligned.m16n8k16.row.col.f32.bf16.bf16.f32 "
        "{%0,%1,%2,%3}, {%4,%5,%6,%7}, {%8,%9}, {%0,%1,%2,%3};"
        : "+f"(c[0]), "+f"(c[1]), "+f"(c[2]), "+f"(c[3])
        : "r"(a[0]), "r"(a[1]), "r"(a[2]), "r"(a[3]), "r"(b0), "r"(b1));
}

__device__ __forceinline__ uint32_t pack_bf16(__nv_bfloat16 a, __nv_bfloat16 b) {
    return (uint32_t)__bfloat16_as_ushort(a) | ((uint32_t)__bfloat16_as_ushort(b) << 16);
}

// ---------------------------------------------------------------------------
// Globals: pre-split W (bf16 hi/lo) + near-tie flag list
// ---------------------------------------------------------------------------
__device__ __nv_bfloat16 g_Whi[E_DIM * H_DIM];
__device__ __nv_bfloat16 g_Wlo[E_DIM * H_DIM];
__device__ int g_flag_count;
__device__ int g_flag_tokens[32768];

__global__ __launch_bounds__(256) void w_split(const float* __restrict__ W) {
    if (blockIdx.x == 0 && threadIdx.x == 0) g_flag_count = 0;
    for (int i = blockIdx.x * 256 + threadIdx.x; i < E_DIM * H_DIM; i += 256 * 256) {
        float w = W[i];
        __nv_bfloat16 hi = __float2bfloat16_rn(w);
        g_Whi[i] = hi;
        g_Wlo[i] = __float2bfloat16_rn(w - __bfloat162float(hi));
    }
}

// ---------------------------------------------------------------------------
// HMMA GEMM (bf16 hi/lo, 3 passes) + fused softmax/top-2/flagging.
// CTA: 128 tokens x 64 experts; warp w owns rows 16w..16w+15.
// ---------------------------------------------------------------------------
__global__ __launch_bounds__(256, 2) void router_gemm_mma(const float* __restrict__ A,
                                                          float* __restrict__ C,
                                                          float* __restrict__ P,
                                                          float* __restrict__ IDX) {
    __shared__ __align__(16) char smem[SMEM_BYTES];
    const uint32_t sb = smem_to_u32(smem);
    float* Cs = (float*)smem;

    const int tid = threadIdx.x;
    const int wid = tid >> 5;
    const int lane = tid & 31;

    const long tokenBase = (long)blockIdx.x * TILE_M;

    float acc[8][4];
#pragma unroll
    for (int j = 0; j < 8; j++)
#pragma unroll
        for (int i = 0; i < 4; i++) acc[j][i] = 0.0f;

    // loader mapping
    const int arow = tid >> 1;            // 0..127
    const int akoff = (tid & 1) * 16;     // elems within chunk
    const int bexp = tid & 63;
    const int bseg = tid >> 6;            // 0..3 (8 k-elems each)
    const float* aptr0 = A + tokenBase * H_DIM + (long)arow * H_DIM + akoff;
    const __nv_bfloat16* whp0 = g_Whi + (long)bexp * H_DIM + bseg * 8;
    const __nv_bfloat16* wlp0 = g_Wlo + (long)bexp * H_DIM + bseg * 8;

    // ldmatrix per-lane address offsets (bytes)
    const uint32_t aRowOff = (uint32_t)((wid * 16 + (lane & 15)) * RSTRIDE +
                                        ((lane >> 4) & 1) * 16);
    const uint32_t bRowOff = (uint32_t)(((lane & 7) + ((lane >> 4) & 1) * 8) * RSTRIDE +
                                        ((lane >> 3) & 1) * 16);

    // prefetch chunk 0
    float4 pa[4];
    uint4 wh, wl;
#pragma unroll
    for (int i = 0; i < 4; i++) pa[i] = *(const float4*)(aptr0 + i * 4);
    wh = *(const uint4*)(whp0);
    wl = *(const uint4*)(wlp0);

    for (int chunk = 0; chunk < NCHUNKS; chunk++) {
        // ---- store stage (convert A fp32 -> bf16 hi/lo) ----
#pragma unroll
        for (int i = 0; i < 4; i++) {
            float x = pa[i].x, y = pa[i].y, z = pa[i].z, w = pa[i].w;
            __nv_bfloat16 hx = __float2bfloat16_rn(x), hy = __float2bfloat16_rn(y);
            __nv_bfloat16 hz = __float2bfloat16_rn(z), hw = __float2bfloat16_rn(w);
            uint2 hi = make_uint2(pack_bf16(hx, hy), pack_bf16(hz, hw));
            __nv_bfloat16 lx = __float2bfloat16_rn(x - __bfloat162float(hx));
            __nv_bfloat16 ly = __float2bfloat16_rn(y - __bfloat162float(hy));
            __nv_bfloat16 lz = __float2bfloat16_rn(z - __bfloat162float(hz));
            __nv_bfloat16 lw = __float2bfloat16_rn(w - __bfloat162float(hw));
            uint2 lo = make_uint2(pack_bf16(lx, ly), pack_bf16(lz, lw));
            const uint32_t off = (uint32_t)(arow * RSTRIDE + (akoff + i * 4) * 2);
            *(uint2*)(smem + OFF_AHI + off) = hi;
            *(uint2*)(smem + OFF_ALO + off) = lo;
        }
        {
            const uint32_t off = (uint32_t)(bexp * RSTRIDE + bseg * 16);
            *(uint4*)(smem + OFF_BHI + off) = wh;
            *(uint4*)(smem + OFF_BLO + off) = wl;
        }
        __syncthreads();

        // ---- prefetch next chunk ----
        if (chunk + 1 < NCHUNKS) {
            const int kb = (chunk + 1) * KCHUNK;
#pragma unroll
            for (int i = 0; i < 4; i++) pa[i] = *(const float4*)(aptr0 + kb + i * 4);
            wh = *(const uint4*)(whp0 + kb);
            wl = *(const uint4*)(wlp0 + kb);
        }

        // ---- compute: 2 k16-steps, 8 n-tiles, 3 passes ----
#pragma unroll
        for (int s = 0; s < 2; s++) {
            const uint32_t koff = s * 32;  // 16 elems * 2B
            uint32_t ah[4], al[4];
            LDSM_X4(ah[0], ah[1], ah[2], ah[3], sb + OFF_AHI + aRowOff + koff);
            LDSM_X4(al[0], al[1], al[2], al[3], sb + OFF_ALO + aRowOff + koff);
#pragma unroll
            for (int jt = 0; jt < 4; jt++) {
                const uint32_t bo = bRowOff + jt * (16 * RSTRIDE) + koff;
                uint32_t bh0, bh1, bh2, bh3, bl0, bl1, bl2, bl3;
                LDSM_X4(bh0, bh1, bh2, bh3, sb + OFF_BHI + bo);
                LDSM_X4(bl0, bl1, bl2, bl3, sb + OFF_BLO + bo);
                mma_bf16(acc[2 * jt], ah, bh0, bh1);
                mma_bf16(acc[2 * jt], ah, bl0, bl1);
                mma_bf16(acc[2 * jt], al, bh0, bh1);
                mma_bf16(acc[2 * jt + 1], ah, bh2, bh3);
                mma_bf16(acc[2 * jt + 1], ah, bl2, bl3);
                mma_bf16(acc[2 * jt + 1], al, bh2, bh3);
            }
        }
        __syncthreads();
    }

    // ---- stage logits to smem [128][CPAD] ----
    {
        const int r0 = wid * 16 + (lane >> 2);
        const int cb = 2 * (lane & 3);
#pragma unroll
        for (int j = 0; j < 8; j++) {
            const int col = j * 8 + cb;
            *(float2*)(Cs + r0 * CPAD + col) = make_float2(acc[j][0], acc[j][1]);
            *(float2*)(Cs + (r0 + 8) * CPAD + col) = make_float2(acc[j][2], acc[j][3]);
        }
    }
    __syncthreads();

    // ---- fused softmax + top-2 + flagging: warp w handles 16 tokens ----
#pragma unroll 1
    for (int t16 = 0; t16 < 16; t16++) {
        const int tok = wid * 16 + t16;
        const float v0 = Cs[tok * CPAD + lane];
        const float v1 = Cs[tok * CPAD + lane + 32];
        const long gtok = tokenBase + tok;

        float* crow = C + gtok * E_DIM;
        crow[lane] = v0;
        crow[lane + 32] = v1;

        float m = fmaxf(v0, v1);
#pragma unroll
        for (int o = 16; o; o >>= 1) m = fmaxf(m, __shfl_xor_sync(0xffffffffu, m, o));

        float e0 = __expf(v0 - m);
        float e1 = __expf(v1 - m);
        float s = e0 + e1;
#pragma unroll
        for (int o = 16; o; o >>= 1) s += __shfl_xor_sync(0xffffffffu, s, o);
        float inv = 1.0f / s;

        float* prow = P + gtok * E_DIM;
        prow[lane] = e0 * inv;
        prow[lane + 32] = e1 * inv;

        // top-1 (ties -> lower index)
        float bv; int bi;
        if (v0 >= v1) { bv = v0; bi = lane; } else { bv = v1; bi = lane + 32; }
#pragma unroll
        for (int o = 16; o; o >>= 1) {
            float ov = __shfl_xor_sync(0xffffffffu, bv, o);
            int   oi = __shfl_xor_sync(0xffffffffu, bi, o);
            if (ov > bv || (ov == bv && oi < bi)) { bv = ov; bi = oi; }
        }
        // top-2
        float c0 = (lane == bi) ? -INFINITY : v0;
        float c1 = (lane + 32 == bi) ? -INFINITY : v1;
        float sv; int si;
        if (c0 >= c1) { sv = c0; si = lane; } else { sv = c1; si = lane + 32; }
#pragma unroll
        for (int o = 16; o; o >>= 1) {
            float ov = __shfl_xor_sync(0xffffffffu, sv, o);
            int   oi = __shfl_xor_sync(0xffffffffu, si, o);
            if (ov > sv || (ov == sv && oi < si)) { sv = ov; si = oi; }
        }
        // top-3 value
        float d0 = (lane == bi || lane == si) ? -INFINITY : v0;
        float d1 = (lane + 32 == bi || lane + 32 == si) ? -INFINITY : v1;
        float tv = fmaxf(d0, d1);
#pragma unroll
        for (int o = 16; o; o >>= 1) tv = fmaxf(tv, __shfl_xor_sync(0xffffffffu, tv, o));

        if (lane == 0) {
            IDX[gtok * 2 + 0] = (float)bi;
            IDX[gtok * 2 + 1] = (float)si;
            if ((bv - sv) < GAP_THRESH || (sv - tv) < GAP_THRESH) {
                int slot = atomicAdd(&g_flag_count, 1);
                if (slot < 32768) g_flag_tokens[slot] = (int)gtok;
            }
        }
    }
}

// ---------------------------------------------------------------------------
// Exact fp64 recomputation for flagged near-tie tokens.
// ---------------------------------------------------------------------------
__global__ __launch_bounds__(64) void refine_ties(const float* __restrict__ A,
                                                  const float* __restrict__ W,
                                                  float* __restrict__ IDX) {
    __shared__ float sA[H_DIM];
    __shared__ double dred[2];
    __shared__ double dred2[2];
    __shared__ float af_s[E_DIM];

    int n = g_flag_count;
    if (n > 32768) n = 32768;

    const int e = threadIdx.x;
    const int lane = e & 31;
    const int wrp = e >> 5;

    for (int it = blockIdx.x; it < n; it += gridDim.x) {
        const int tok = g_flag_tokens[it];
        const float* arow = A + (long)tok * H_DIM;
        for (int k = threadIdx.x * 4; k < H_DIM; k += 64 * 4)
            *(float4*)(sA + k) = *(const float4*)(arow + k);
        __syncthreads();

        const float* wrow = W + (long)e * H_DIM;
        double a0 = 0, a1 = 0, a2 = 0, a3 = 0, a4 = 0, a5 = 0, a6 = 0, a7 = 0;
#pragma unroll 4
        for (int k = 0; k < H_DIM; k += 8) {
            float4 w0 = *(const float4*)(wrow + k);
            float4 w1 = *(const float4*)(wrow + k + 4);
            a0 = fma((double)sA[k + 0], (double)w0.x, a0);
            a1 = fma((double)sA[k + 1], (double)w0.y, a1);
            a2 = fma((double)sA[k + 2], (double)w0.z, a2);
            a3 = fma((double)sA[k + 3], (double)w0.w, a3);
            a4 = fma((double)sA[k + 4], (double)w1.x, a4);
            a5 = fma((double)sA[k + 5], (double)w1.y, a5);
            a6 = fma((double)sA[k + 6], (double)w1.z, a6);
            a7 = fma((double)sA[k + 7], (double)w1.w, a7);
        }
        double l = ((a0 + a1) + (a2 + a3)) + ((a4 + a5) + (a6 + a7));

        double mv = l;
#pragma unroll
        for (int o = 16; o; o >>= 1) {
            double ov = __shfl_xor_sync(0xffffffffu, mv, o);
            mv = ov > mv ? ov : mv;
        }
        if (lane == 0) dred[wrp] = mv;
        __syncthreads();
        const double m = dred[0] > dred[1] ? dred[0] : dred[1];

        const double ex = exp(l - m);
        double sm = ex;
#pragma unroll
        for (int o = 16; o; o >>= 1) sm += __shfl_xor_sync(0xffffffffu, sm, o);
        if (lane == 0) dred2[wrp] = sm;
        __syncthreads();
        const double s = dred2[0] + dred2[1];

        af_s[e] = (float)(ex / s);
        __syncthreads();

        if (e == 0) {
            int bi = 0;
#pragma unroll
            for (int i = 1; i < E_DIM; i++)
                if (af_s[i] > af_s[bi]) bi = i;
            int si = (bi == 0) ? 1 : 0;
#pragma unroll
            for (int i = 0; i < E_DIM; i++) {
                if (i == bi || i == si) continue;
                if (af_s[i] > af_s[si]) si = i;
            }
            IDX[(long)tok * 2 + 0] = (float)bi;
            IDX[(long)tok * 2 + 1] = (float)si;
        }
        __syncthreads();
    }
}

// ---------------------------------------------------------------------------
// d_out: [logits T*64 | affinities T*64 | indices-as-float T*2], fp32.
// ---------------------------------------------------------------------------
extern "C" void kernel_launch(void* const* d_in, const int* in_sizes, int n_in,
                              void* d_out, int out_size) {
    const float* A = (const float*)d_in[0];
    const float* W = (const float*)d_in[1];
    const int T = in_sizes[0] / H_DIM;  // 32768

    float* out = (float*)d_out;
    float* logits = out;
    float* affin  = out + (long)T * E_DIM;
    float* idx    = out + 2L * T * E_DIM;

    w_split<<<256, 256>>>(W);
    router_gemm_mma<<<T / TILE_M, 256>>>(A, logits, affin, idx);
    refine_ties<<<128, 64>>>(A, W, idx);
}

// round 7
// speedup vs baseline: 1.7512x; 1.1494x over previous
#include <cuda_runtime.h>
#include <cuda_bf16.h>
#include <cstdint>
#include <math.h>

#define H_DIM 4096
#define E_DIM 64
#define TILE_M 128
#define KCHUNK 32
#define NCHUNKS (H_DIM / KCHUNK)   // 128
#define GAP_THRESH 5e-4f
#define CPAD 68

// stage layout (bytes), SW64-swizzled tight tiles (64 B rows)
#define OFF_AHI 0
#define OFF_ALO 8192
#define OFF_BHI 16384
#define OFF_BLO 20480
#define STAGE_BYTES 24576
#define SMEM_BYTES 49152          // 2 stages; epilogue C-stage overlays

// byte offset of (row, 16B-chunk c) in a SW64-swizzled 64B-row tile
#define SWZ(r, c) ((uint32_t)((r) * 64 + ((((c) ^ (((r) >> 1) & 3))) << 4)))

__device__ __forceinline__ uint32_t smem_to_u32(const void* p) {
    uint32_t a;
    asm("{ .reg .u64 t; cvta.to.shared.u64 t, %1; cvt.u32.u64 %0, t; }" : "=r"(a) : "l"(p));
    return a;
}

#define LDSM_X4(r0, r1, r2, r3, addr)                                          \
    asm volatile("ldmatrix.sync.aligned.m8n8.x4.shared.b16 {%0,%1,%2,%3}, [%4];" \
                 : "=r"(r0), "=r"(r1), "=r"(r2), "=r"(r3) : "r"(addr))

__device__ __forceinline__ void mma_bf16(float* c, const uint32_t* a,
                                         uint32_t b0, uint32_t b1) {
    asm volatile(
        "mma.sync.aligned.m16n8k16.row.col.f32.bf16.bf16.f32 "
        "{%0,%1,%2,%3}, {%4,%5,%6,%7}, {%8,%9}, {%0,%1,%2,%3};"
        : "+f"(c[0]), "+f"(c[1]), "+f"(c[2]), "+f"(c[3])
        : "r"(a[0]), "r"(a[1]), "r"(a[2]), "r"(a[3]), "r"(b0), "r"(b1));
}

__device__ __forceinline__ uint32_t bf2(float a, float b) {
    __nv_bfloat162 t = __floats2bfloat162_rn(a, b);
    return *(uint32_t*)&t;
}

// split 8 fp32 -> 16B bf16 hi + 16B bf16 lo
__device__ __forceinline__ void split8(const float4 p0, const float4 p1,
                                       uint4& hi, uint4& lo) {
    hi.x = bf2(p0.x, p0.y); hi.y = bf2(p0.z, p0.w);
    hi.z = bf2(p1.x, p1.y); hi.w = bf2(p1.z, p1.w);
    float hx = __uint_as_float(hi.x << 16), hy = __uint_as_float(hi.x & 0xffff0000u);
    float hz = __uint_as_float(hi.y << 16), hw = __uint_as_float(hi.y & 0xffff0000u);
    lo.x = bf2(p0.x - hx, p0.y - hy); lo.y = bf2(p0.z - hz, p0.w - hw);
    hx = __uint_as_float(hi.z << 16); hy = __uint_as_float(hi.z & 0xffff0000u);
    hz = __uint_as_float(hi.w << 16); hw = __uint_as_float(hi.w & 0xffff0000u);
    lo.z = bf2(p1.x - hx, p1.y - hy); lo.w = bf2(p1.z - hz, p1.w - hw);
}

// ---------------------------------------------------------------------------
// Globals: pre-split W (bf16 hi/lo) + near-tie flag list
// ---------------------------------------------------------------------------
__device__ __nv_bfloat16 g_Whi[E_DIM * H_DIM];
__device__ __nv_bfloat16 g_Wlo[E_DIM * H_DIM];
__device__ int g_flag_count;
__device__ int g_flag_tokens[32768];

__global__ __launch_bounds__(256) void w_split(const float* __restrict__ W) {
    if (blockIdx.x == 0 && threadIdx.x == 0) g_flag_count = 0;
    for (int i = blockIdx.x * 256 + threadIdx.x; i < E_DIM * H_DIM; i += 256 * 256) {
        float w = W[i];
        __nv_bfloat16 hi = __float2bfloat16_rn(w);
        g_Whi[i] = hi;
        g_Wlo[i] = __float2bfloat16_rn(w - __bfloat162float(hi));
    }
}

// ---------------------------------------------------------------------------
// HMMA GEMM (bf16 hi/lo, 3 passes), double-buffered + fused epilogue.
// CTA: 128 tokens x 64 experts; warp w owns token rows 16w..16w+15.
// ---------------------------------------------------------------------------
__global__ __launch_bounds__(256, 2) void router_gemm_mma(const float* __restrict__ A,
                                                          float* __restrict__ C,
                                                          float* __restrict__ P,
                                                          float* __restrict__ IDX) {
    __shared__ __align__(16) char smem[SMEM_BYTES];
    const uint32_t sb = smem_to_u32(smem);
    float* Cs = (float*)smem;

    const int tid = threadIdx.x;
    const int wid = tid >> 5;
    const int lane = tid & 31;
    const long tokenBase = (long)blockIdx.x * TILE_M;

    float acc[8][4];
#pragma unroll
    for (int j = 0; j < 8; j++)
#pragma unroll
        for (int i = 0; i < 4; i++) acc[j][i] = 0.0f;

    // loader mapping: thread t handles A groups {t, t+256}, B group t.
    // group g -> row g>>2, 16B chunk g&3 (8 fp32 elems)
    const int lrow = tid >> 2;           // 0..63
    const int lc = tid & 3;              // chunk
    const int lel = lc * 8;              // elem offset in chunk dim
    const float* aP0 = A + (tokenBase + lrow) * H_DIM + lel;
    const float* aP1 = A + (tokenBase + lrow + 64) * H_DIM + lel;
    const __nv_bfloat16* whP = g_Whi + (long)lrow * H_DIM + lel;
    const __nv_bfloat16* wlP = g_Wlo + (long)lrow * H_DIM + lel;
    const uint32_t sA0 = SWZ(lrow, lc), sA1 = SWZ(lrow + 64, lc), sB = SWZ(lrow, lc);

    // ldmatrix lane addressing
    const int arow = wid * 16 + (lane & 15);
    const uint32_t axr = (uint32_t)((arow >> 1) & 3);
    const uint32_t ahalf = (uint32_t)((lane >> 4) & 1);
    const int ebase = (lane & 7) + ((lane >> 4) & 1) * 8;
    const uint32_t bxr = (uint32_t)((ebase >> 1) & 3);
    const uint32_t bhalf = (uint32_t)((lane >> 3) & 1);

    // ---- prologue: chunk 0 ----
    float4 p00 = *(const float4*)(aP0), p01 = *(const float4*)(aP0 + 4);
    float4 p10 = *(const float4*)(aP1), p11 = *(const float4*)(aP1 + 4);
    uint4 wh = *(const uint4*)(whP), wl = *(const uint4*)(wlP);
    {
        uint4 h0, l0, h1, l1;
        split8(p00, p01, h0, l0);
        split8(p10, p11, h1, l1);
        *(uint4*)(smem + OFF_AHI + sA0) = h0;
        *(uint4*)(smem + OFF_ALO + sA0) = l0;
        *(uint4*)(smem + OFF_AHI + sA1) = h1;
        *(uint4*)(smem + OFF_ALO + sA1) = l1;
        *(uint4*)(smem + OFF_BHI + sB) = wh;
        *(uint4*)(smem + OFF_BLO + sB) = wl;
    }
    __syncthreads();

    for (int chunk = 0; chunk < NCHUNKS; chunk++) {
        const uint32_t cb = (uint32_t)((chunk & 1) * STAGE_BYTES);
        const uint32_t nb = (uint32_t)(((chunk + 1) & 1) * STAGE_BYTES);
        const bool more = (chunk + 1 < NCHUNKS);

        // prefetch next chunk into registers (overlap with MMA)
        if (more) {
            const int kb = (chunk + 1) * KCHUNK;
            p00 = *(const float4*)(aP0 + kb); p01 = *(const float4*)(aP0 + kb + 4);
            p10 = *(const float4*)(aP1 + kb); p11 = *(const float4*)(aP1 + kb + 4);
            wh = *(const uint4*)(whP + kb);   wl = *(const uint4*)(wlP + kb);
        }

        // compute on current buffer: 2 k16-steps x 24 MMA
#pragma unroll
        for (int s = 0; s < 2; s++) {
            uint32_t ah[4], al[4];
            {
                const uint32_t ach = (uint32_t)(2 * s) + ahalf;
                const uint32_t ao = (uint32_t)(arow * 64) + ((ach ^ axr) << 4);
                LDSM_X4(ah[0], ah[1], ah[2], ah[3], sb + cb + OFF_AHI + ao);
                LDSM_X4(al[0], al[1], al[2], al[3], sb + cb + OFF_ALO + ao);
            }
            uint32_t bh[16], bl[16];
#pragma unroll
            for (int jt = 0; jt < 4; jt++) {
                const int erow = jt * 16 + ebase;
                const uint32_t bch = (uint32_t)(2 * s) + bhalf;
                const uint32_t bo = (uint32_t)(erow * 64) + ((bch ^ bxr) << 4);
                LDSM_X4(bh[4 * jt], bh[4 * jt + 1], bh[4 * jt + 2], bh[4 * jt + 3],
                        sb + cb + OFF_BHI + bo);
                LDSM_X4(bl[4 * jt], bl[4 * jt + 1], bl[4 * jt + 2], bl[4 * jt + 3],
                        sb + cb + OFF_BLO + bo);
            }
            // pass hi*hi
#pragma unroll
            for (int jt = 0; jt < 4; jt++) {
                mma_bf16(acc[2 * jt], ah, bh[4 * jt], bh[4 * jt + 1]);
                mma_bf16(acc[2 * jt + 1], ah, bh[4 * jt + 2], bh[4 * jt + 3]);
            }
            // pass hi*lo
#pragma unroll
            for (int jt = 0; jt < 4; jt++) {
                mma_bf16(acc[2 * jt], ah, bl[4 * jt], bl[4 * jt + 1]);
                mma_bf16(acc[2 * jt + 1], ah, bl[4 * jt + 2], bl[4 * jt + 3]);
            }
            // pass lo*hi
#pragma unroll
            for (int jt = 0; jt < 4; jt++) {
                mma_bf16(acc[2 * jt], al, bh[4 * jt], bh[4 * jt + 1]);
                mma_bf16(acc[2 * jt + 1], al, bh[4 * jt + 2], bh[4 * jt + 3]);
            }
        }

        // convert + store next chunk into alternate buffer
        if (more) {
            uint4 h0, l0, h1, l1;
            split8(p00, p01, h0, l0);
            split8(p10, p11, h1, l1);
            *(uint4*)(smem + nb + OFF_AHI + sA0) = h0;
            *(uint4*)(smem + nb + OFF_ALO + sA0) = l0;
            *(uint4*)(smem + nb + OFF_AHI + sA1) = h1;
            *(uint4*)(smem + nb + OFF_ALO + sA1) = l1;
            *(uint4*)(smem + nb + OFF_BHI + sB) = wh;
            *(uint4*)(smem + nb + OFF_BLO + sB) = wl;
        }
        __syncthreads();
    }

    // ---- stage logits to smem [128][CPAD] (overlays stage buffers) ----
    {
        const int r0 = wid * 16 + (lane >> 2);
        const int cbo = 2 * (lane & 3);
#pragma unroll
        for (int j = 0; j < 8; j++) {
            const int col = j * 8 + cbo;
            *(float2*)(Cs + r0 * CPAD + col) = make_float2(acc[j][0], acc[j][1]);
            *(float2*)(Cs + (r0 + 8) * CPAD + col) = make_float2(acc[j][2], acc[j][3]);
        }
    }
    __syncthreads();

    // ---- fused softmax + top-2 + flagging: warp w handles 16 tokens ----
#pragma unroll 1
    for (int t16 = 0; t16 < 16; t16++) {
        const int tok = wid * 16 + t16;
        const float v0 = Cs[tok * CPAD + lane];
        const float v1 = Cs[tok * CPAD + lane + 32];
        const long gtok = tokenBase + tok;

        float* crow = C + gtok * E_DIM;
        crow[lane] = v0;
        crow[lane + 32] = v1;

        float m = fmaxf(v0, v1);
#pragma unroll
        for (int o = 16; o; o >>= 1) m = fmaxf(m, __shfl_xor_sync(0xffffffffu, m, o));

        float e0 = __expf(v0 - m);
        float e1 = __expf(v1 - m);
        float s = e0 + e1;
#pragma unroll
        for (int o = 16; o; o >>= 1) s += __shfl_xor_sync(0xffffffffu, s, o);
        float inv = 1.0f / s;

        float* prow = P + gtok * E_DIM;
        prow[lane] = e0 * inv;
        prow[lane + 32] = e1 * inv;

        float bv; int bi;
        if (v0 >= v1) { bv = v0; bi = lane; } else { bv = v1; bi = lane + 32; }
#pragma unroll
        for (int o = 16; o; o >>= 1) {
            float ov = __shfl_xor_sync(0xffffffffu, bv, o);
            int   oi = __shfl_xor_sync(0xffffffffu, bi, o);
            if (ov > bv || (ov == bv && oi < bi)) { bv = ov; bi = oi; }
        }
        float c0 = (lane == bi) ? -INFINITY : v0;
        float c1 = (lane + 32 == bi) ? -INFINITY : v1;
        float sv; int si;
        if (c0 >= c1) { sv = c0; si = lane; } else { sv = c1; si = lane + 32; }
#pragma unroll
        for (int o = 16; o; o >>= 1) {
            float ov = __shfl_xor_sync(0xffffffffu, sv, o);
            int   oi = __shfl_xor_sync(0xffffffffu, si, o);
            if (ov > sv || (ov == sv && oi < si)) { sv = ov; si = oi; }
        }
        float d0 = (lane == bi || lane == si) ? -INFINITY : v0;
        float d1 = (lane + 32 == bi || lane + 32 == si) ? -INFINITY : v1;
        float tv = fmaxf(d0, d1);
#pragma unroll
        for (int o = 16; o; o >>= 1) tv = fmaxf(tv, __shfl_xor_sync(0xffffffffu, tv, o));

        if (lane == 0) {
            IDX[gtok * 2 + 0] = (float)bi;
            IDX[gtok * 2 + 1] = (float)si;
            if ((bv - sv) < GAP_THRESH || (sv - tv) < GAP_THRESH) {
                int slot = atomicAdd(&g_flag_count, 1);
                if (slot < 32768) g_flag_tokens[slot] = (int)gtok;
            }
        }
    }
}

// ---------------------------------------------------------------------------
// Exact fp64 recomputation for flagged near-tie tokens.
// ---------------------------------------------------------------------------
__global__ __launch_bounds__(64) void refine_ties(const float* __restrict__ A,
                                                  const float* __restrict__ W,
                                                  float* __restrict__ IDX) {
    __shared__ float sA[H_DIM];
    __shared__ double dred[2];
    __shared__ double dred2[2];
    __shared__ float af_s[E_DIM];

    int n = g_flag_count;
    if (n > 32768) n = 32768;

    const int e = threadIdx.x;
    const int lane = e & 31;
    const int wrp = e >> 5;

    for (int it = blockIdx.x; it < n; it += gridDim.x) {
        const int tok = g_flag_tokens[it];
        const float* arow = A + (long)tok * H_DIM;
        for (int k = threadIdx.x * 4; k < H_DIM; k += 64 * 4)
            *(float4*)(sA + k) = *(const float4*)(arow + k);
        __syncthreads();

        const float* wrow = W + (long)e * H_DIM;
        double a0 = 0, a1 = 0, a2 = 0, a3 = 0, a4 = 0, a5 = 0, a6 = 0, a7 = 0;
#pragma unroll 4
        for (int k = 0; k < H_DIM; k += 8) {
            float4 w0 = *(const float4*)(wrow + k);
            float4 w1 = *(const float4*)(wrow + k + 4);
            a0 = fma((double)sA[k + 0], (double)w0.x, a0);
            a1 = fma((double)sA[k + 1], (double)w0.y, a1);
            a2 = fma((double)sA[k + 2], (double)w0.z, a2);
            a3 = fma((double)sA[k + 3], (double)w0.w, a3);
            a4 = fma((double)sA[k + 4], (double)w1.x, a4);
            a5 = fma((double)sA[k + 5], (double)w1.y, a5);
            a6 = fma((double)sA[k + 6], (double)w1.z, a6);
            a7 = fma((double)sA[k + 7], (double)w1.w, a7);
        }
        double l = ((a0 + a1) + (a2 + a3)) + ((a4 + a5) + (a6 + a7));

        double mv = l;
#pragma unroll
        for (int o = 16; o; o >>= 1) {
            double ov = __shfl_xor_sync(0xffffffffu, mv, o);
            mv = ov > mv ? ov : mv;
        }
        if (lane == 0) dred[wrp] = mv;
        __syncthreads();
        const double m = dred[0] > dred[1] ? dred[0] : dred[1];

        const double ex = exp(l - m);
        double sm = ex;
#pragma unroll
        for (int o = 16; o; o >>= 1) sm += __shfl_xor_sync(0xffffffffu, sm, o);
        if (lane == 0) dred2[wrp] = sm;
        __syncthreads();
        const double s = dred2[0] + dred2[1];

        af_s[e] = (float)(ex / s);
        __syncthreads();

        if (e == 0) {
            int bi = 0;
#pragma unroll
            for (int i = 1; i < E_DIM; i++)
                if (af_s[i] > af_s[bi]) bi = i;
            int si = (bi == 0) ? 1 : 0;
#pragma unroll
            for (int i = 0; i < E_DIM; i++) {
                if (i == bi || i == si) continue;
                if (af_s[i] > af_s[si]) si = i;
            }
            IDX[(long)tok * 2 + 0] = (float)bi;
            IDX[(long)tok * 2 + 1] = (float)si;
        }
        __syncthreads();
    }
}

// ---------------------------------------------------------------------------
// d_out: [logits T*64 | affinities T*64 | indices-as-float T*2], fp32.
// ---------------------------------------------------------------------------
extern "C" void kernel_launch(void* const* d_in, const int* in_sizes, int n_in,
                              void* d_out, int out_size) {
    const float* A = (const float*)d_in[0];
    const float* W = (const float*)d_in[1];
    const int T = in_sizes[0] / H_DIM;  // 32768

    float* out = (float*)d_out;
    float* logits = out;
    float* affin  = out + (long)T * E_DIM;
    float* idx    = out + 2L * T * E_DIM;

    w_split<<<256, 256>>>(W);
    router_gemm_mma<<<T / TILE_M, 256>>>(A, logits, affin, idx);
    refine_ties<<<128, 64>>>(A, W, idx);
}